// round 3
// baseline (speedup 1.0000x reference)
#include <cuda_runtime.h>

// ============================================================================
// UniGATConv on GB300.
//   Xe  = (segment_mean_over_edges(X)) @ W^T            [E, 256]   (linearity)
//   a_e = leaky_relu(sum_c Xe[e,h,c]*att[h,c])          [E, 8]
//   per-vertex segment softmax over incident edges, weighted sum of Xe rows,
//   then L2 row-normalize.
// CSR (edge->members, vertex->incident edges) built on device each call via
// histogram + 3-pass scan + atomic fill. No float atomics anywhere.
// ============================================================================

#define H_       8
#define C_       32
#define HC       256
#define IN_DIM   256
#define NMAX     50000
#define EMAX     10000
#define NNZMAX   320000
#define EB       ((EMAX + 1023) / 1024)   // 10 scan chunks for edges
#define VB       ((NMAX + 1023) / 1024)   // 49 scan chunks for vertices
#define NEG_SLOPE 0.2f

// ---------------- scratch (static device globals; no allocations) -----------
__device__ int g_is64;
__device__ int g_cnt_e[EMAX];
__device__ int g_fill_e[EMAX];
__device__ int g_off_e[EMAX];
__device__ int g_cnt_v[NMAX];
__device__ int g_fill_v[NMAX];
__device__ int g_off_v[NMAX];
__device__ int g_emem[NNZMAX];   // per-edge member vertex ids
__device__ int g_vmem[NNZMAX];   // per-vertex incident edge ids (with multiplicity)
__device__ __align__(16) float g_SumX[EMAX * HC];   // mean_e(X) (pre-scaled by 1/cnt)
__device__ __align__(16) float g_Xe[EMAX * HC];     // edge features after linear
__device__ float g_alpha[EMAX * H_];                // leaky_relu(attention logit)
__device__ int g_bsum_e[EB + 1];
__device__ int g_bsum_v[VB + 1];

// ---------------- dtype detection: int64 vs int32 indices --------------------
// If buffer is int64 with nonneg values < 2^31, every odd 32-bit word is 0.
__global__ void k_detect64(const int* idx32, int nnz) {
    __shared__ int any;
    if (threadIdx.x == 0) any = 0;
    __syncthreads();
    int lim = min(nnz / 2, 2048);
    for (int j = threadIdx.x; j < lim; j += blockDim.x)
        if (idx32[2 * j + 1] != 0) any = 1;   // benign race
    __syncthreads();
    if (threadIdx.x == 0) g_is64 = (any == 0) ? 1 : 0;
}

__device__ __forceinline__ int load_idx(const void* p, int j, int is64) {
    return is64 ? (int)((const long long*)p)[j] : ((const int*)p)[j];
}

// ---------------- zero counters ----------------------------------------------
__global__ void k_zero(int E, int N) {
    int i = blockIdx.x * blockDim.x + threadIdx.x;
    int stride = gridDim.x * blockDim.x;
    for (int j = i; j < E; j += stride) { g_cnt_e[j] = 0; g_fill_e[j] = 0; }
    for (int j = i; j < N; j += stride) { g_cnt_v[j] = 0; g_fill_v[j] = 0; }
}

// ---------------- histogram ---------------------------------------------------
__global__ void k_hist(const void* vert, const void* edges, int nnz) {
    int is64 = g_is64;
    int i = blockIdx.x * blockDim.x + threadIdx.x;
    int stride = gridDim.x * blockDim.x;
    for (int j = i; j < nnz; j += stride) {
        atomicAdd(&g_cnt_v[load_idx(vert, j, is64)], 1);
        atomicAdd(&g_cnt_e[load_idx(edges, j, is64)], 1);
    }
}

// ---------------- 3-pass exclusive scan (both arrays in one grid) -------------
__global__ void k_scan1(int nE, int nV) {
    __shared__ int s[1024];
    bool isE  = blockIdx.x < EB;
    int chunk = isE ? blockIdx.x : blockIdx.x - EB;
    const int* cnt = isE ? g_cnt_e : g_cnt_v;
    int* off  = isE ? g_off_e : g_off_v;
    int* bsum = isE ? g_bsum_e : g_bsum_v;
    int n = isE ? nE : nV;
    int t = threadIdx.x;
    int idx = chunk * 1024 + t;
    int val = (idx < n) ? cnt[idx] : 0;
    s[t] = val;
    __syncthreads();
    for (int o = 1; o < 1024; o <<= 1) {
        int x = (t >= o) ? s[t - o] : 0;
        __syncthreads();
        s[t] += x;
        __syncthreads();
    }
    if (idx < n) off[idx] = s[t] - val;   // exclusive
    if (t == 1023) bsum[chunk] = s[1023];
}

__global__ void k_scan2() {
    if (threadIdx.x == 0) {
        int* b = (blockIdx.x == 0) ? g_bsum_e : g_bsum_v;
        int nb = (blockIdx.x == 0) ? EB : VB;
        int run = 0;
        for (int i = 0; i < nb; i++) { int x = b[i]; b[i] = run; run += x; }
        b[nb] = run;
    }
}

__global__ void k_scan3(int nE, int nV) {
    bool isE  = blockIdx.x < EB;
    int chunk = isE ? blockIdx.x : blockIdx.x - EB;
    int* off  = isE ? g_off_e : g_off_v;
    const int* bsum = isE ? g_bsum_e : g_bsum_v;
    int n = isE ? nE : nV;
    int idx = chunk * 1024 + threadIdx.x;
    if (idx < n) off[idx] += bsum[chunk];
}

// ---------------- fill member lists ------------------------------------------
__global__ void k_fill(const void* vert, const void* edges, int nnz) {
    int is64 = g_is64;
    int i = blockIdx.x * blockDim.x + threadIdx.x;
    int stride = gridDim.x * blockDim.x;
    for (int j = i; j < nnz; j += stride) {
        int v = load_idx(vert, j, is64);
        int e = load_idx(edges, j, is64);
        int p = atomicAdd(&g_fill_e[e], 1);
        g_emem[g_off_e[e] + p] = v;
        int q = atomicAdd(&g_fill_v[v], 1);
        g_vmem[g_off_v[v] + q] = e;
    }
}

// ---------------- per-edge mean of X (input space; 1 block / edge) ------------
__global__ void k_sumx(const float* __restrict__ X) {
    int e = blockIdx.x;
    int t = threadIdx.x;
    int cnt = g_cnt_e[e], base = g_off_e[e];
    float a0 = 0.f, a1 = 0.f, a2 = 0.f, a3 = 0.f;
    int j = 0;
    for (; j + 4 <= cnt; j += 4) {
        int v0 = g_emem[base + j + 0];
        int v1 = g_emem[base + j + 1];
        int v2 = g_emem[base + j + 2];
        int v3 = g_emem[base + j + 3];
        a0 += X[v0 * IN_DIM + t];
        a1 += X[v1 * IN_DIM + t];
        a2 += X[v2 * IN_DIM + t];
        a3 += X[v3 * IN_DIM + t];
    }
    for (; j < cnt; j++) a0 += X[g_emem[base + j] * IN_DIM + t];
    float inv = 1.0f / (float)(cnt > 0 ? cnt : 1);
    g_SumX[e * HC + t] = (a0 + a1 + a2 + a3) * inv;
}

// ---------------- Xe = SumX @ W^T (fp32 tiled GEMM, 64x64x16, 4x4 utile) ------
__global__ void k_gemm(const float* __restrict__ W, int E) {
    __shared__ float As[16][65];   // [k][m], padded vs STS conflicts
    __shared__ float Bs[16][64];   // [k][o], float4-readable
    int tid = threadIdx.x;
    int tx = tid & 15, ty = tid >> 4;
    int row0 = blockIdx.y * 64, col0 = blockIdx.x * 64;
    float c[4][4] = {};
    int r = tid >> 2, sseg = tid & 3;

    for (int k0 = 0; k0 < IN_DIM; k0 += 16) {
        float4 av;
        int arow = row0 + r;
        if (arow < E) av = *(const float4*)&g_SumX[arow * HC + k0 + sseg * 4];
        else          av = make_float4(0.f, 0.f, 0.f, 0.f);
        As[sseg * 4 + 0][r] = av.x;
        As[sseg * 4 + 1][r] = av.y;
        As[sseg * 4 + 2][r] = av.z;
        As[sseg * 4 + 3][r] = av.w;
        float4 bv = *(const float4*)&W[(col0 + r) * IN_DIM + k0 + sseg * 4];
        Bs[sseg * 4 + 0][r] = bv.x;
        Bs[sseg * 4 + 1][r] = bv.y;
        Bs[sseg * 4 + 2][r] = bv.z;
        Bs[sseg * 4 + 3][r] = bv.w;
        __syncthreads();
#pragma unroll
        for (int kk = 0; kk < 16; kk++) {
            float a0 = As[kk][ty * 4 + 0];
            float a1 = As[kk][ty * 4 + 1];
            float a2 = As[kk][ty * 4 + 2];
            float a3 = As[kk][ty * 4 + 3];
            float4 b = *(const float4*)&Bs[kk][tx * 4];
            c[0][0] += a0 * b.x; c[0][1] += a0 * b.y; c[0][2] += a0 * b.z; c[0][3] += a0 * b.w;
            c[1][0] += a1 * b.x; c[1][1] += a1 * b.y; c[1][2] += a1 * b.z; c[1][3] += a1 * b.w;
            c[2][0] += a2 * b.x; c[2][1] += a2 * b.y; c[2][2] += a2 * b.z; c[2][3] += a2 * b.w;
            c[3][0] += a3 * b.x; c[3][1] += a3 * b.y; c[3][2] += a3 * b.z; c[3][3] += a3 * b.w;
        }
        __syncthreads();
    }
#pragma unroll
    for (int i = 0; i < 4; i++) {
        int row = row0 + ty * 4 + i;
        if (row < E)
            *(float4*)&g_Xe[row * HC + col0 + tx * 4] =
                make_float4(c[i][0], c[i][1], c[i][2], c[i][3]);
    }
}

// ---------------- attention logits + leaky relu (1 warp / edge) --------------
__global__ void k_alpha(const float* __restrict__ att, int E) {
    int gw = (blockIdx.x * blockDim.x + threadIdx.x) >> 5;
    int lane = threadIdx.x & 31;
    if (gw >= E) return;
#pragma unroll
    for (int h = 0; h < H_; h++) {
        float x = g_Xe[gw * HC + h * C_ + lane] * att[h * C_ + lane];
#pragma unroll
        for (int o = 16; o > 0; o >>= 1) x += __shfl_down_sync(0xffffffffu, x, o);
        if (lane == 0) g_alpha[gw * H_ + h] = (x > 0.f) ? x : NEG_SLOPE * x;
    }
}

// ---------------- per-vertex softmax + weighted sum + L2 norm -----------------
__global__ void k_final(float* __restrict__ out, int N) {
    int v = blockIdx.x;
    int t = threadIdx.x;      // t = h*32 + c
    int h = t >> 5;
    __shared__ float red[8];
    int deg = g_cnt_v[v], base = g_off_v[v];
    float val = 0.f;
    if (deg > 0) {
        float m = -3.4e38f;
        for (int j = 0; j < deg; j++)
            m = fmaxf(m, g_alpha[g_vmem[base + j] * H_ + h]);
        float s = 0.f, acc = 0.f;
        for (int j = 0; j < deg; j++) {
            int e = g_vmem[base + j];
            float w = __expf(g_alpha[e * H_ + h] - m);
            s += w;
            acc = fmaf(w, g_Xe[e * HC + t], acc);
        }
        val = acc / (s + 1e-16f);
    }
    float ss = val * val;
#pragma unroll
    for (int o = 16; o > 0; o >>= 1) ss += __shfl_down_sync(0xffffffffu, ss, o);
    if ((t & 31) == 0) red[t >> 5] = ss;
    __syncthreads();
    if (t == 0) {
        float x = 0.f;
#pragma unroll
        for (int i = 0; i < 8; i++) x += red[i];
        red[0] = x;
    }
    __syncthreads();
    float tot = red[0];
    float scale = (tot > 0.f) ? rsqrtf(tot) : 0.f;
    out[v * HC + t] = val * scale;
}

// ---------------- host launch -------------------------------------------------
extern "C" void kernel_launch(void* const* d_in, const int* in_sizes, int n_in,
                              void* d_out, int out_size) {
    const float* X    = (const float*)d_in[0];
    const float* W    = (const float*)d_in[1];
    const float* att  = (const float*)d_in[2];
    const void*  vert = d_in[3];
    const void*  edge = d_in[4];

    int N   = in_sizes[0] / IN_DIM;
    int NNZ = in_sizes[3];
    int E   = EMAX;                 // fixed problem instance (num_edges = 10000)
    if (N   > NMAX)   N   = NMAX;
    if (NNZ > NNZMAX) NNZ = NNZMAX;

    k_detect64<<<1, 256>>>((const int*)vert, NNZ);
    k_zero<<<256, 256>>>(E, N);
    int hg = (NNZ + 255) / 256;
    if (hg > 2048) hg = 2048;
    k_hist<<<hg, 256>>>(vert, edge, NNZ);
    k_scan1<<<EB + VB, 1024>>>(E, N);
    k_scan2<<<2, 32>>>();
    k_scan3<<<EB + VB, 1024>>>(E, N);
    k_fill<<<hg, 256>>>(vert, edge, NNZ);
    k_sumx<<<E, 256>>>(X);
    dim3 gg(HC / 64, (E + 63) / 64);
    k_gemm<<<gg, 256>>>(W, E);
    k_alpha<<<(E * 32 + 255) / 256, 256>>>(att, E);
    k_final<<<N, 256>>>((float*)d_out, N);
}

// round 4
// speedup vs baseline: 1.4764x; 1.4764x over previous
#include <cuda_runtime.h>

// ============================================================================
// UniGATConv on GB300 (R3):
//  - float4-vectorized edge-mean gather and vertex softmax/scatter (LSU-issue
//    relief; both gathers are L2-resident)
//  - GEMM inner loop on packed fma.rn.f32x2 (2 MACs/instr, halves FFMA-pipe load)
//  - detect64 merged into zero; scan3 eliminated (bsum folded into consumers)
// ============================================================================

#define H_       8
#define C_       32
#define HC       256
#define IN_DIM   256
#define NMAX     50000
#define EMAX     10000
#define NNZMAX   320000
#define EB       ((EMAX + 1023) / 1024)   // 10 edge scan chunks
#define VB       ((NMAX + 1023) / 1024)   // 49 vertex scan chunks
#define NEG_SLOPE 0.2f

// ---- packed fp32x2 helpers (sm_100+ PTX; not emitted by ptxas from C++) ----
#define PACK2(d, lo, hi) asm("mov.b64 %0, {%1, %2};" : "=l"(d) : "f"(lo), "f"(hi))
#define FMA2(d, a, b)    asm("fma.rn.f32x2 %0, %1, %2, %0;" : "+l"(d) : "l"(a), "l"(b))
#define UNPACK2(lo, hi, s) asm("mov.b64 {%0, %1}, %2;" : "=f"(lo), "=f"(hi) : "l"(s))

// ---------------- scratch (static device globals; no allocations) -----------
__device__ int g_is64;
__device__ int g_cnt_e[EMAX];
__device__ int g_fill_e[EMAX];
__device__ int g_off_e[EMAX];          // chunk-local exclusive prefix
__device__ int g_cnt_v[NMAX];
__device__ int g_fill_v[NMAX];
__device__ int g_off_v[NMAX];          // chunk-local exclusive prefix
__device__ int g_emem[NNZMAX];         // per-edge member vertex ids
__device__ int g_vmem[NNZMAX];         // per-vertex incident edge ids
__device__ __align__(16) float g_SumX[EMAX * HC];   // mean_e(X)
__device__ __align__(16) float g_Xe[EMAX * HC];     // edge features after linear
__device__ float g_alpha[EMAX * H_];                // leaky_relu(attention logit)
__device__ int g_bsum_e[EB + 1];
__device__ int g_bsum_v[VB + 1];

// ---------------- zero counters + int64/int32 index detection ----------------
// If the index buffer is int64 with values < 2^31, every odd 32-bit word is 0.
__global__ void k_zero(const int* idx32, int nnz, int E, int N) {
    if (blockIdx.x == 0) {
        __shared__ int any;
        if (threadIdx.x == 0) any = 0;
        __syncthreads();
        int lim = min(nnz / 2, 2048);
        for (int j = threadIdx.x; j < lim; j += blockDim.x)
            if (idx32[2 * j + 1] != 0) any = 1;   // benign race
        __syncthreads();
        if (threadIdx.x == 0) g_is64 = (any == 0) ? 1 : 0;
    }
    int i = blockIdx.x * blockDim.x + threadIdx.x;
    int stride = gridDim.x * blockDim.x;
    for (int j = i; j < E; j += stride) { g_cnt_e[j] = 0; g_fill_e[j] = 0; }
    for (int j = i; j < N; j += stride) { g_cnt_v[j] = 0; g_fill_v[j] = 0; }
}

__device__ __forceinline__ int load_idx(const void* p, int j, int is64) {
    return is64 ? (int)((const long long*)p)[j] : ((const int*)p)[j];
}

// ---------------- histogram ---------------------------------------------------
__global__ void k_hist(const void* vert, const void* edges, int nnz) {
    int is64 = g_is64;
    int i = blockIdx.x * blockDim.x + threadIdx.x;
    int stride = gridDim.x * blockDim.x;
    for (int j = i; j < nnz; j += stride) {
        atomicAdd(&g_cnt_v[load_idx(vert, j, is64)], 1);
        atomicAdd(&g_cnt_e[load_idx(edges, j, is64)], 1);
    }
}

// ---------------- 2-pass scan (chunk-local prefix + serial chunk sums) --------
__global__ void k_scan1(int nE, int nV) {
    __shared__ int s[1024];
    bool isE  = blockIdx.x < EB;
    int chunk = isE ? blockIdx.x : blockIdx.x - EB;
    const int* cnt = isE ? g_cnt_e : g_cnt_v;
    int* off  = isE ? g_off_e : g_off_v;
    int* bsum = isE ? g_bsum_e : g_bsum_v;
    int n = isE ? nE : nV;
    int t = threadIdx.x;
    int idx = chunk * 1024 + t;
    int val = (idx < n) ? cnt[idx] : 0;
    s[t] = val;
    __syncthreads();
    for (int o = 1; o < 1024; o <<= 1) {
        int x = (t >= o) ? s[t - o] : 0;
        __syncthreads();
        s[t] += x;
        __syncthreads();
    }
    if (idx < n) off[idx] = s[t] - val;   // exclusive, chunk-local
    if (t == 1023) bsum[chunk] = s[1023];
}

__global__ void k_scan2() {
    if (threadIdx.x == 0) {
        int* b = (blockIdx.x == 0) ? g_bsum_e : g_bsum_v;
        int nb = (blockIdx.x == 0) ? EB : VB;
        int run = 0;
        for (int i = 0; i < nb; i++) { int x = b[i]; b[i] = run; run += x; }
        b[nb] = run;
    }
}

// ---------------- fill member lists (bsum folded in) --------------------------
__global__ void k_fill(const void* vert, const void* edges, int nnz) {
    int is64 = g_is64;
    int i = blockIdx.x * blockDim.x + threadIdx.x;
    int stride = gridDim.x * blockDim.x;
    for (int j = i; j < nnz; j += stride) {
        int v = load_idx(vert, j, is64);
        int e = load_idx(edges, j, is64);
        int p = atomicAdd(&g_fill_e[e], 1);
        g_emem[g_off_e[e] + g_bsum_e[e >> 10] + p] = v;
        int q = atomicAdd(&g_fill_v[v], 1);
        g_vmem[g_off_v[v] + g_bsum_v[v >> 10] + q] = e;
    }
}

// ---------------- per-edge mean of X (4 edges/block, 64 threads/edge, f4) -----
__global__ void k_sumx(const float* __restrict__ X) {
    int e = blockIdx.x * 4 + (threadIdx.x >> 6);
    int lane = threadIdx.x & 63;                   // channel group: [4*lane, 4*lane+4)
    int cnt = g_cnt_e[e];
    int base = g_off_e[e] + g_bsum_e[e >> 10];
    float4 a0 = make_float4(0.f, 0.f, 0.f, 0.f), a1 = a0, a2 = a0, a3 = a0;
    int j = 0;
    for (; j + 4 <= cnt; j += 4) {
        int v0 = g_emem[base + j + 0];
        int v1 = g_emem[base + j + 1];
        int v2 = g_emem[base + j + 2];
        int v3 = g_emem[base + j + 3];
        float4 x0 = ((const float4*)&X[v0 * IN_DIM])[lane];
        float4 x1 = ((const float4*)&X[v1 * IN_DIM])[lane];
        float4 x2 = ((const float4*)&X[v2 * IN_DIM])[lane];
        float4 x3 = ((const float4*)&X[v3 * IN_DIM])[lane];
        a0.x += x0.x; a0.y += x0.y; a0.z += x0.z; a0.w += x0.w;
        a1.x += x1.x; a1.y += x1.y; a1.z += x1.z; a1.w += x1.w;
        a2.x += x2.x; a2.y += x2.y; a2.z += x2.z; a2.w += x2.w;
        a3.x += x3.x; a3.y += x3.y; a3.z += x3.z; a3.w += x3.w;
    }
    for (; j < cnt; j++) {
        float4 x0 = ((const float4*)&X[g_emem[base + j] * IN_DIM])[lane];
        a0.x += x0.x; a0.y += x0.y; a0.z += x0.z; a0.w += x0.w;
    }
    float inv = 1.0f / (float)(cnt > 0 ? cnt : 1);
    float4 r;
    r.x = (a0.x + a1.x + a2.x + a3.x) * inv;
    r.y = (a0.y + a1.y + a2.y + a3.y) * inv;
    r.z = (a0.z + a1.z + a2.z + a3.z) * inv;
    r.w = (a0.w + a1.w + a2.w + a3.w) * inv;
    ((float4*)&g_SumX[e * HC])[lane] = r;
}

// ---------------- Xe = SumX @ W^T (64x64x16 tile, 4x4 utile, fma.f32x2) -------
__global__ void k_gemm(const float* __restrict__ W, int E) {
    __shared__ __align__(16) float As[16][68];   // [k][m], 16B-aligned rows
    __shared__ __align__(16) float Bs[16][64];   // [k][o]
    int tid = threadIdx.x;
    int tx = tid & 15, ty = tid >> 4;
    int row0 = blockIdx.y * 64, col0 = blockIdx.x * 64;
    unsigned long long c2[4][2] = {};            // 4 rows x 2 col-pairs (f32x2)
    int r = tid >> 2, sseg = tid & 3;

    for (int k0 = 0; k0 < IN_DIM; k0 += 16) {
        float4 av;
        int arow = row0 + r;
        if (arow < E) av = *(const float4*)&g_SumX[arow * HC + k0 + sseg * 4];
        else          av = make_float4(0.f, 0.f, 0.f, 0.f);
        As[sseg * 4 + 0][r] = av.x;
        As[sseg * 4 + 1][r] = av.y;
        As[sseg * 4 + 2][r] = av.z;
        As[sseg * 4 + 3][r] = av.w;
        float4 bv = *(const float4*)&W[(col0 + r) * IN_DIM + k0 + sseg * 4];
        Bs[sseg * 4 + 0][r] = bv.x;
        Bs[sseg * 4 + 1][r] = bv.y;
        Bs[sseg * 4 + 2][r] = bv.z;
        Bs[sseg * 4 + 3][r] = bv.w;
        __syncthreads();
#pragma unroll
        for (int kk = 0; kk < 16; kk++) {
            float4 a = *(const float4*)&As[kk][ty * 4];
            float4 b = *(const float4*)&Bs[kk][tx * 4];
            unsigned long long b01, b23, ap;
            PACK2(b01, b.x, b.y);
            PACK2(b23, b.z, b.w);
            PACK2(ap, a.x, a.x); FMA2(c2[0][0], ap, b01); FMA2(c2[0][1], ap, b23);
            PACK2(ap, a.y, a.y); FMA2(c2[1][0], ap, b01); FMA2(c2[1][1], ap, b23);
            PACK2(ap, a.z, a.z); FMA2(c2[2][0], ap, b01); FMA2(c2[2][1], ap, b23);
            PACK2(ap, a.w, a.w); FMA2(c2[3][0], ap, b01); FMA2(c2[3][1], ap, b23);
        }
        __syncthreads();
    }
#pragma unroll
    for (int i = 0; i < 4; i++) {
        int row = row0 + ty * 4 + i;
        if (row < E) {
            float x0, x1, x2, x3;
            UNPACK2(x0, x1, c2[i][0]);
            UNPACK2(x2, x3, c2[i][1]);
            *(float4*)&g_Xe[row * HC + col0 + tx * 4] = make_float4(x0, x1, x2, x3);
        }
    }
}

// ---------------- attention logits + leaky relu (1 warp / edge) --------------
__global__ void k_alpha(const float* __restrict__ att, int E) {
    int gw = (blockIdx.x * blockDim.x + threadIdx.x) >> 5;
    int lane = threadIdx.x & 31;
    if (gw >= E) return;
#pragma unroll
    for (int h = 0; h < H_; h++) {
        float x = g_Xe[gw * HC + h * C_ + lane] * att[h * C_ + lane];
#pragma unroll
        for (int o = 16; o > 0; o >>= 1) x += __shfl_down_sync(0xffffffffu, x, o);
        if (lane == 0) g_alpha[gw * H_ + h] = (x > 0.f) ? x : NEG_SLOPE * x;
    }
}

// ---------------- per-vertex softmax + weighted sum + L2 norm -----------------
// 4 vertices / block, 64 threads / vertex, float4 per thread.
__global__ void k_final(float* __restrict__ out, int N) {
    int g = threadIdx.x >> 6;                  // vertex slot in block (0..3)
    int v = blockIdx.x * 4 + g;
    int lane = threadIdx.x & 63;               // channels [4*lane, 4*lane+4)
    int h = lane >> 3;
    __shared__ float red[8];                   // one partial per warp
    float4 val = make_float4(0.f, 0.f, 0.f, 0.f);
    int deg = g_cnt_v[v];
    int base = g_off_v[v] + g_bsum_v[v >> 10];
    if (deg > 0) {
        float m = -3.4e38f;
        for (int j = 0; j < deg; j++)
            m = fmaxf(m, g_alpha[g_vmem[base + j] * H_ + h]);
        float s = 0.f;
        for (int j = 0; j < deg; j++) {
            int e = g_vmem[base + j];
            float w = __expf(g_alpha[e * H_ + h] - m);
            s += w;
            float4 xe = ((const float4*)&g_Xe[e * HC])[lane];
            val.x = fmaf(w, xe.x, val.x);
            val.y = fmaf(w, xe.y, val.y);
            val.z = fmaf(w, xe.z, val.z);
            val.w = fmaf(w, xe.w, val.w);
        }
        float inv = 1.0f / (s + 1e-16f);
        val.x *= inv; val.y *= inv; val.z *= inv; val.w *= inv;
    }
    float ss = val.x * val.x + val.y * val.y + val.z * val.z + val.w * val.w;
#pragma unroll
    for (int o = 16; o > 0; o >>= 1) ss += __shfl_down_sync(0xffffffffu, ss, o);
    if ((threadIdx.x & 31) == 0) red[threadIdx.x >> 5] = ss;
    __syncthreads();
    float tot = red[2 * g] + red[2 * g + 1];
    float scale = (tot > 0.f) ? rsqrtf(tot) : 0.f;
    val.x *= scale; val.y *= scale; val.z *= scale; val.w *= scale;
    ((float4*)&out[v * HC])[lane] = val;
}

// ---------------- host launch -------------------------------------------------
extern "C" void kernel_launch(void* const* d_in, const int* in_sizes, int n_in,
                              void* d_out, int out_size) {
    const float* X    = (const float*)d_in[0];
    const float* W    = (const float*)d_in[1];
    const float* att  = (const float*)d_in[2];
    const void*  vert = d_in[3];
    const void*  edge = d_in[4];

    int N   = in_sizes[0] / IN_DIM;
    int NNZ = in_sizes[3];
    int E   = EMAX;                 // fixed problem instance (num_edges = 10000)
    if (N   > NMAX)   N   = NMAX;
    if (NNZ > NNZMAX) NNZ = NNZMAX;

    k_zero<<<256, 256>>>((const int*)vert, NNZ, E, N);
    int hg = (NNZ + 255) / 256;
    if (hg > 2048) hg = 2048;
    k_hist<<<hg, 256>>>(vert, edge, NNZ);
    k_scan1<<<EB + VB, 1024>>>(E, N);
    k_scan2<<<2, 32>>>();
    k_fill<<<hg, 256>>>(vert, edge, NNZ);
    k_sumx<<<E / 4, 256>>>(X);
    dim3 gg(HC / 64, (E + 63) / 64);
    k_gemm<<<gg, 256>>>(W, E);
    k_alpha<<<(E * 32 + 255) / 256, 256>>>(att, E);
    k_final<<<N / 4, 256>>>((float*)d_out, N);
}

// round 5
// speedup vs baseline: 1.5379x; 1.0417x over previous
#include <cuda_runtime.h>

// ============================================================================
// UniGATConv on GB300 (R4):
//  - k_scan2 eliminated: chunk-sum scan runs in k_scan1's last arriving block
//    (threadfence + atomic ticket), warp-parallel loads instead of a serial
//    latency chain.
//  - k_scan1 rewritten as two-level warp-shfl scan (2 barriers, not 20).
//  - k_alpha fused into k_gemm epilogue (64-col tile == 2 whole heads).
//  Launches: zero, hist, scan1, fill, sumx, gemm, final  (7).
// ============================================================================

#define H_       8
#define C_       32
#define HC       256
#define IN_DIM   256
#define NMAX     50000
#define EMAX     10000
#define NNZMAX   320000
#define EB       ((EMAX + 1023) / 1024)   // 10 edge scan chunks
#define VB       ((NMAX + 1023) / 1024)   // 49 vertex scan chunks
#define NEG_SLOPE 0.2f

// ---- packed fp32x2 helpers (sm_100+ PTX; not emitted by ptxas from C++) ----
#define PACK2(d, lo, hi) asm("mov.b64 %0, {%1, %2};" : "=l"(d) : "f"(lo), "f"(hi))
#define FMA2(d, a, b)    asm("fma.rn.f32x2 %0, %1, %2, %0;" : "+l"(d) : "l"(a), "l"(b))
#define UNPACK2(lo, hi, s) asm("mov.b64 {%0, %1}, %2;" : "=f"(lo), "=f"(hi) : "l"(s))

// ---------------- scratch (static device globals; no allocations) -----------
__device__ int g_is64;
__device__ int g_scan_done;
__device__ int g_cnt_e[EMAX];
__device__ int g_fill_e[EMAX];
__device__ int g_off_e[EMAX];          // chunk-local exclusive prefix
__device__ int g_cnt_v[NMAX];
__device__ int g_fill_v[NMAX];
__device__ int g_off_v[NMAX];          // chunk-local exclusive prefix
__device__ int g_emem[NNZMAX];         // per-edge member vertex ids
__device__ int g_vmem[NNZMAX];         // per-vertex incident edge ids
__device__ __align__(16) float g_SumX[EMAX * HC];   // mean_e(X)
__device__ __align__(16) float g_Xe[EMAX * HC];     // edge features after linear
__device__ float g_alpha[EMAX * H_];                // leaky_relu(attention logit)
__device__ int g_bsum_e[EB];           // raw chunk sums -> exclusive prefixes
__device__ int g_bsum_v[VB];

__device__ __forceinline__ int wscan(int v) {   // warp inclusive scan
    int lane = threadIdx.x & 31;
#pragma unroll
    for (int o = 1; o < 32; o <<= 1) {
        int n = __shfl_up_sync(0xffffffffu, v, o);
        if (lane >= o) v += n;
    }
    return v;
}

// ---------------- zero counters + int64/int32 index detection ----------------
__global__ void k_zero(const int* idx32, int nnz, int E, int N) {
    if (blockIdx.x == 0) {
        __shared__ int any;
        if (threadIdx.x == 0) { any = 0; g_scan_done = 0; }
        __syncthreads();
        int lim = min(nnz / 2, 2048);
        for (int j = threadIdx.x; j < lim; j += blockDim.x)
            if (idx32[2 * j + 1] != 0) any = 1;   // benign race
        __syncthreads();
        if (threadIdx.x == 0) g_is64 = (any == 0) ? 1 : 0;
    }
    int i = blockIdx.x * blockDim.x + threadIdx.x;
    int stride = gridDim.x * blockDim.x;
    for (int j = i; j < E; j += stride) { g_cnt_e[j] = 0; g_fill_e[j] = 0; }
    for (int j = i; j < N; j += stride) { g_cnt_v[j] = 0; g_fill_v[j] = 0; }
}

__device__ __forceinline__ int load_idx(const void* p, int j, int is64) {
    return is64 ? (int)((const long long*)p)[j] : ((const int*)p)[j];
}

// ---------------- histogram ---------------------------------------------------
__global__ void k_hist(const void* vert, const void* edges, int nnz) {
    int is64 = g_is64;
    int i = blockIdx.x * blockDim.x + threadIdx.x;
    int stride = gridDim.x * blockDim.x;
    for (int j = i; j < nnz; j += stride) {
        atomicAdd(&g_cnt_v[load_idx(vert, j, is64)], 1);
        atomicAdd(&g_cnt_e[load_idx(edges, j, is64)], 1);
    }
}

// ------- scan: chunk-local prefix; last block scans the chunk sums ------------
__global__ void k_scan1(int nE, int nV) {
    __shared__ int wsum[32];
    __shared__ int islast;
    bool isE  = blockIdx.x < EB;
    int chunk = isE ? blockIdx.x : blockIdx.x - EB;
    const int* cnt = isE ? g_cnt_e : g_cnt_v;
    int* off  = isE ? g_off_e : g_off_v;
    int* bsum = isE ? g_bsum_e : g_bsum_v;
    int n = isE ? nE : nV;
    int t = threadIdx.x, lane = t & 31, w = t >> 5;
    int idx = chunk * 1024 + t;
    int val = (idx < n) ? cnt[idx] : 0;
    int inc = wscan(val);
    if (lane == 31) wsum[w] = inc;
    __syncthreads();
    if (w == 0) wsum[lane] = wscan(wsum[lane]);
    __syncthreads();
    int pref = ((w > 0) ? wsum[w - 1] : 0) + inc - val;   // exclusive, chunk-local
    if (idx < n) off[idx] = pref;
    if (t == 1023) { bsum[chunk] = wsum[31]; __threadfence(); }
    __syncthreads();
    if (t == 0) islast = (atomicAdd(&g_scan_done, 1) == EB + VB - 1);
    __syncthreads();
    if (islast && w < 2) {
        __threadfence();   // acquire: see all blocks' bsum stores
        if (w == 0) {      // edges: EB <= 32, one warp-scan
            int v = (lane < EB) ? g_bsum_e[lane] : 0;
            int i2 = wscan(v);
            if (lane < EB) g_bsum_e[lane] = i2 - v;
        } else {           // vertices: VB <= 64, two tiles with carry
            int carry = 0;
#pragma unroll
            for (int tt = 0; tt < 2; tt++) {
                int id = tt * 32 + lane;
                int v = (id < VB) ? g_bsum_v[id] : 0;
                int i2 = wscan(v);
                if (id < VB) g_bsum_v[id] = carry + i2 - v;
                carry += __shfl_sync(0xffffffffu, i2, 31);
            }
        }
    }
}

// ---------------- fill member lists (bsum folded in) --------------------------
__global__ void k_fill(const void* vert, const void* edges, int nnz) {
    int is64 = g_is64;
    int i = blockIdx.x * blockDim.x + threadIdx.x;
    int stride = gridDim.x * blockDim.x;
    for (int j = i; j < nnz; j += stride) {
        int v = load_idx(vert, j, is64);
        int e = load_idx(edges, j, is64);
        int p = atomicAdd(&g_fill_e[e], 1);
        g_emem[g_off_e[e] + g_bsum_e[e >> 10] + p] = v;
        int q = atomicAdd(&g_fill_v[v], 1);
        g_vmem[g_off_v[v] + g_bsum_v[v >> 10] + q] = e;
    }
}

// ---------------- per-edge mean of X (4 edges/block, 64 threads/edge, f4) -----
__global__ void k_sumx(const float* __restrict__ X) {
    int e = blockIdx.x * 4 + (threadIdx.x >> 6);
    int lane = threadIdx.x & 63;                   // channels [4*lane, 4*lane+4)
    int cnt = g_cnt_e[e];
    int base = g_off_e[e] + g_bsum_e[e >> 10];
    float4 a0 = make_float4(0.f, 0.f, 0.f, 0.f), a1 = a0, a2 = a0, a3 = a0;
    int j = 0;
    for (; j + 4 <= cnt; j += 4) {
        int v0 = g_emem[base + j + 0];
        int v1 = g_emem[base + j + 1];
        int v2 = g_emem[base + j + 2];
        int v3 = g_emem[base + j + 3];
        float4 x0 = ((const float4*)&X[v0 * IN_DIM])[lane];
        float4 x1 = ((const float4*)&X[v1 * IN_DIM])[lane];
        float4 x2 = ((const float4*)&X[v2 * IN_DIM])[lane];
        float4 x3 = ((const float4*)&X[v3 * IN_DIM])[lane];
        a0.x += x0.x; a0.y += x0.y; a0.z += x0.z; a0.w += x0.w;
        a1.x += x1.x; a1.y += x1.y; a1.z += x1.z; a1.w += x1.w;
        a2.x += x2.x; a2.y += x2.y; a2.z += x2.z; a2.w += x2.w;
        a3.x += x3.x; a3.y += x3.y; a3.z += x3.z; a3.w += x3.w;
    }
    for (; j < cnt; j++) {
        float4 x0 = ((const float4*)&X[g_emem[base + j] * IN_DIM])[lane];
        a0.x += x0.x; a0.y += x0.y; a0.z += x0.z; a0.w += x0.w;
    }
    float inv = 1.0f / (float)(cnt > 0 ? cnt : 1);
    float4 r;
    r.x = (a0.x + a1.x + a2.x + a3.x) * inv;
    r.y = (a0.y + a1.y + a2.y + a3.y) * inv;
    r.z = (a0.z + a1.z + a2.z + a3.z) * inv;
    r.w = (a0.w + a1.w + a2.w + a3.w) * inv;
    ((float4*)&g_SumX[e * HC])[lane] = r;
}

// ------- Xe = SumX @ W^T + fused attention logits (alpha) ---------------------
// 64x64x16 tile, 4x4 utile on fma.f32x2. A 64-col tile spans exactly heads
// {2*bx, 2*bx+1}, so alpha is finished here with an 8-lane shfl reduction.
__global__ void k_gemm(const float* __restrict__ W, const float* __restrict__ att,
                       int E) {
    __shared__ __align__(16) float As[16][68];
    __shared__ __align__(16) float Bs[16][64];
    int tid = threadIdx.x;
    int tx = tid & 15, ty = tid >> 4;
    int lane = tid & 31;
    int row0 = blockIdx.y * 64, col0 = blockIdx.x * 64;
    unsigned long long c2[4][2] = {};
    int r = tid >> 2, sseg = tid & 3;
    float4 attv = *(const float4*)&att[col0 + tx * 4];

    for (int k0 = 0; k0 < IN_DIM; k0 += 16) {
        float4 av;
        int arow = row0 + r;
        if (arow < E) av = *(const float4*)&g_SumX[arow * HC + k0 + sseg * 4];
        else          av = make_float4(0.f, 0.f, 0.f, 0.f);
        As[sseg * 4 + 0][r] = av.x;
        As[sseg * 4 + 1][r] = av.y;
        As[sseg * 4 + 2][r] = av.z;
        As[sseg * 4 + 3][r] = av.w;
        float4 bv = *(const float4*)&W[(col0 + r) * IN_DIM + k0 + sseg * 4];
        Bs[sseg * 4 + 0][r] = bv.x;
        Bs[sseg * 4 + 1][r] = bv.y;
        Bs[sseg * 4 + 2][r] = bv.z;
        Bs[sseg * 4 + 3][r] = bv.w;
        __syncthreads();
#pragma unroll
        for (int kk = 0; kk < 16; kk++) {
            float4 a = *(const float4*)&As[kk][ty * 4];
            float4 b = *(const float4*)&Bs[kk][tx * 4];
            unsigned long long b01, b23, ap;
            PACK2(b01, b.x, b.y);
            PACK2(b23, b.z, b.w);
            PACK2(ap, a.x, a.x); FMA2(c2[0][0], ap, b01); FMA2(c2[0][1], ap, b23);
            PACK2(ap, a.y, a.y); FMA2(c2[1][0], ap, b01); FMA2(c2[1][1], ap, b23);
            PACK2(ap, a.z, a.z); FMA2(c2[2][0], ap, b01); FMA2(c2[2][1], ap, b23);
            PACK2(ap, a.w, a.w); FMA2(c2[3][0], ap, b01); FMA2(c2[3][1], ap, b23);
        }
        __syncthreads();
    }
#pragma unroll
    for (int i = 0; i < 4; i++) {
        int row = row0 + ty * 4 + i;
        float x0, x1, x2, x3;
        UNPACK2(x0, x1, c2[i][0]);
        UNPACK2(x2, x3, c2[i][1]);
        if (row < E)
            *(float4*)&g_Xe[row * HC + col0 + tx * 4] = make_float4(x0, x1, x2, x3);
        // fused alpha: partial dot with att, reduce across the 8 lanes of one head
        float s = x0 * attv.x + x1 * attv.y + x2 * attv.z + x3 * attv.w;
        s += __shfl_xor_sync(0xffffffffu, s, 1);
        s += __shfl_xor_sync(0xffffffffu, s, 2);
        s += __shfl_xor_sync(0xffffffffu, s, 4);
        if ((lane & 7) == 0 && row < E) {
            int head = (col0 >> 5) + ((lane >> 3) & 1);
            g_alpha[row * H_ + head] = (s > 0.f) ? s : NEG_SLOPE * s;
        }
    }
}

// ---------------- per-vertex softmax + weighted sum + L2 norm -----------------
// 4 vertices / block, 64 threads / vertex, float4 per thread.
__global__ void k_final(float* __restrict__ out, int N) {
    int g = threadIdx.x >> 6;                  // vertex slot in block (0..3)
    int v = blockIdx.x * 4 + g;
    int lane = threadIdx.x & 63;               // channels [4*lane, 4*lane+4)
    int h = lane >> 3;
    __shared__ float red[8];
    float4 val = make_float4(0.f, 0.f, 0.f, 0.f);
    int deg = g_cnt_v[v];
    int base = g_off_v[v] + g_bsum_v[v >> 10];
    if (deg > 0) {
        float m = -3.4e38f;
        for (int j = 0; j < deg; j++)
            m = fmaxf(m, g_alpha[g_vmem[base + j] * H_ + h]);
        float s = 0.f;
        for (int j = 0; j < deg; j++) {
            int e = g_vmem[base + j];
            float w = __expf(g_alpha[e * H_ + h] - m);
            s += w;
            float4 xe = ((const float4*)&g_Xe[e * HC])[lane];
            val.x = fmaf(w, xe.x, val.x);
            val.y = fmaf(w, xe.y, val.y);
            val.z = fmaf(w, xe.z, val.z);
            val.w = fmaf(w, xe.w, val.w);
        }
        float inv = 1.0f / (s + 1e-16f);
        val.x *= inv; val.y *= inv; val.z *= inv; val.w *= inv;
    }
    float ss = val.x * val.x + val.y * val.y + val.z * val.z + val.w * val.w;
#pragma unroll
    for (int o = 16; o > 0; o >>= 1) ss += __shfl_down_sync(0xffffffffu, ss, o);
    if ((threadIdx.x & 31) == 0) red[threadIdx.x >> 5] = ss;
    __syncthreads();
    float tot = red[2 * g] + red[2 * g + 1];
    float scale = (tot > 0.f) ? rsqrtf(tot) : 0.f;
    val.x *= scale; val.y *= scale; val.z *= scale; val.w *= scale;
    ((float4*)&out[v * HC])[lane] = val;
}

// ---------------- host launch -------------------------------------------------
extern "C" void kernel_launch(void* const* d_in, const int* in_sizes, int n_in,
                              void* d_out, int out_size) {
    const float* X    = (const float*)d_in[0];
    const float* W    = (const float*)d_in[1];
    const float* att  = (const float*)d_in[2];
    const void*  vert = d_in[3];
    const void*  edge = d_in[4];

    int N   = in_sizes[0] / IN_DIM;
    int NNZ = in_sizes[3];
    int E   = EMAX;                 // fixed problem instance (num_edges = 10000)
    if (N   > NMAX)   N   = NMAX;
    if (NNZ > NNZMAX) NNZ = NNZMAX;

    k_zero<<<256, 256>>>((const int*)vert, NNZ, E, N);
    int hg = (NNZ + 255) / 256;
    if (hg > 2048) hg = 2048;
    k_hist<<<hg, 256>>>(vert, edge, NNZ);
    k_scan1<<<EB + VB, 1024>>>(E, N);
    k_fill<<<hg, 256>>>(vert, edge, NNZ);
    k_sumx<<<E / 4, 256>>>(X);
    dim3 gg(HC / 64, (E + 63) / 64);
    k_gemm<<<gg, 256>>>(W, att, E);
    k_final<<<N / 4, 256>>>((float*)d_out, N);
}

// round 7
// speedup vs baseline: 1.5906x; 1.0342x over previous
#include <cuda_runtime.h>

// ============================================================================
// UniGATConv on GB300 (R5):
//  - rank trick: k_hist's atomicAdd return value IS the within-segment rank;
//    stored to g_rank_{e,v}, so k_fill is atomic-free (pure gather/scatter)
//    and the g_fill counters + their zeroing are gone.
//  - k_final softmax/gather loops unrolled x4 with batched index loads (MLP).
//  Launches: zero, hist, scan1, fill, sumx, gemm(+alpha), final  (7).
// ============================================================================

#define H_       8
#define C_       32
#define HC       256
#define IN_DIM   256
#define NMAX     50000
#define EMAX     10000
#define NNZMAX   320000
#define EB       ((EMAX + 1023) / 1024)   // 10 edge scan chunks
#define VB       ((NMAX + 1023) / 1024)   // 49 vertex scan chunks
#define NEG_SLOPE 0.2f

// ---- packed fp32x2 helpers (sm_100+ PTX; not emitted by ptxas from C++) ----
#define PACK2(d, lo, hi) asm("mov.b64 %0, {%1, %2};" : "=l"(d) : "f"(lo), "f"(hi))
#define FMA2(d, a, b)    asm("fma.rn.f32x2 %0, %1, %2, %0;" : "+l"(d) : "l"(a), "l"(b))
#define UNPACK2(lo, hi, s) asm("mov.b64 {%0, %1}, %2;" : "=f"(lo), "=f"(hi) : "l"(s))

// ---------------- scratch (static device globals; no allocations) -----------
__device__ int g_is64;
__device__ int g_scan_done;
__device__ int g_cnt_e[EMAX];
__device__ int g_off_e[EMAX];          // chunk-local exclusive prefix
__device__ int g_cnt_v[NMAX];
__device__ int g_off_v[NMAX];          // chunk-local exclusive prefix
__device__ int g_rank_e[NNZMAX];       // incidence rank within its edge
__device__ int g_rank_v[NNZMAX];       // incidence rank within its vertex
__device__ int g_emem[NNZMAX];         // per-edge member vertex ids
__device__ int g_vmem[NNZMAX];         // per-vertex incident edge ids
__device__ __align__(16) float g_SumX[EMAX * HC];   // mean_e(X)
__device__ __align__(16) float g_Xe[EMAX * HC];     // edge features after linear
__device__ float g_alpha[EMAX * H_];                // leaky_relu(attention logit)
__device__ int g_bsum_e[EB];           // raw chunk sums -> exclusive prefixes
__device__ int g_bsum_v[VB];

__device__ __forceinline__ int wscan(int v) {   // warp inclusive scan
    int lane = threadIdx.x & 31;
#pragma unroll
    for (int o = 1; o < 32; o <<= 1) {
        int n = __shfl_up_sync(0xffffffffu, v, o);
        if (lane >= o) v += n;
    }
    return v;
}

// ---------------- zero counters + int64/int32 index detection ----------------
__global__ void k_zero(const int* idx32, int nnz, int E, int N) {
    if (blockIdx.x == 0) {
        __shared__ int any;
        if (threadIdx.x == 0) { any = 0; g_scan_done = 0; }
        __syncthreads();
        int lim = min(nnz / 2, 2048);
        for (int j = threadIdx.x; j < lim; j += blockDim.x)
            if (idx32[2 * j + 1] != 0) any = 1;   // benign race
        __syncthreads();
        if (threadIdx.x == 0) g_is64 = (any == 0) ? 1 : 0;
    }
    int i = blockIdx.x * blockDim.x + threadIdx.x;
    int stride = gridDim.x * blockDim.x;
    for (int j = i; j < E; j += stride) g_cnt_e[j] = 0;
    for (int j = i; j < N; j += stride) g_cnt_v[j] = 0;
}

__device__ __forceinline__ int load_idx(const void* p, int j, int is64) {
    return is64 ? (int)((const long long*)p)[j] : ((const int*)p)[j];
}

// -------- histogram; atomic return value = within-segment rank ---------------
__global__ void k_hist(const void* vert, const void* edges, int nnz) {
    int is64 = g_is64;
    int i = blockIdx.x * blockDim.x + threadIdx.x;
    int stride = gridDim.x * blockDim.x;
    for (int j = i; j < nnz; j += stride) {
        g_rank_v[j] = atomicAdd(&g_cnt_v[load_idx(vert, j, is64)], 1);
        g_rank_e[j] = atomicAdd(&g_cnt_e[load_idx(edges, j, is64)], 1);
    }
}

// ------- scan: chunk-local prefix; last block scans the chunk sums ------------
__global__ void k_scan1(int nE, int nV) {
    __shared__ int wsum[32];
    __shared__ int islast;
    bool isE  = blockIdx.x < EB;
    int chunk = isE ? blockIdx.x : blockIdx.x - EB;
    const int* cnt = isE ? g_cnt_e : g_cnt_v;
    int* off  = isE ? g_off_e : g_off_v;
    int* bsum = isE ? g_bsum_e : g_bsum_v;
    int n = isE ? nE : nV;
    int t = threadIdx.x, lane = t & 31, w = t >> 5;
    int idx = chunk * 1024 + t;
    int val = (idx < n) ? cnt[idx] : 0;
    int inc = wscan(val);
    if (lane == 31) wsum[w] = inc;
    __syncthreads();
    if (w == 0) wsum[lane] = wscan(wsum[lane]);
    __syncthreads();
    int pref = ((w > 0) ? wsum[w - 1] : 0) + inc - val;   // exclusive, chunk-local
    if (idx < n) off[idx] = pref;
    if (t == 1023) { bsum[chunk] = wsum[31]; __threadfence(); }
    __syncthreads();
    if (t == 0) islast = (atomicAdd(&g_scan_done, 1) == EB + VB - 1);
    __syncthreads();
    if (islast && w < 2) {
        __threadfence();   // acquire: see all blocks' bsum stores
        if (w == 0) {      // edges: EB <= 32, one warp-scan
            int v = (lane < EB) ? g_bsum_e[lane] : 0;
            int i2 = wscan(v);
            if (lane < EB) g_bsum_e[lane] = i2 - v;
        } else {           // vertices: VB <= 64, two tiles with carry
            int carry = 0;
#pragma unroll
            for (int tt = 0; tt < 2; tt++) {
                int id = tt * 32 + lane;
                int v = (id < VB) ? g_bsum_v[id] : 0;
                int i2 = wscan(v);
                if (id < VB) g_bsum_v[id] = carry + i2 - v;
                carry += __shfl_sync(0xffffffffu, i2, 31);
            }
        }
    }
}

// ---------------- fill member lists (atomic-free: ranks precomputed) ----------
__global__ void k_fill(const void* vert, const void* edges, int nnz) {
    int is64 = g_is64;
    int i = blockIdx.x * blockDim.x + threadIdx.x;
    int stride = gridDim.x * blockDim.x;
    for (int j = i; j < nnz; j += stride) {
        int v = load_idx(vert, j, is64);
        int e = load_idx(edges, j, is64);
        g_emem[g_off_e[e] + g_bsum_e[e >> 10] + g_rank_e[j]] = v;
        g_vmem[g_off_v[v] + g_bsum_v[v >> 10] + g_rank_v[j]] = e;
    }
}

// ---------------- per-edge mean of X (4 edges/block, 64 threads/edge, f4) -----
__global__ void k_sumx(const float* __restrict__ X) {
    int e = blockIdx.x * 4 + (threadIdx.x >> 6);
    int lane = threadIdx.x & 63;                   // channels [4*lane, 4*lane+4)
    int cnt = g_cnt_e[e];
    int base = g_off_e[e] + g_bsum_e[e >> 10];
    float4 a0 = make_float4(0.f, 0.f, 0.f, 0.f), a1 = a0, a2 = a0, a3 = a0;
    int j = 0;
    for (; j + 4 <= cnt; j += 4) {
        int v0 = g_emem[base + j + 0];
        int v1 = g_emem[base + j + 1];
        int v2 = g_emem[base + j + 2];
        int v3 = g_emem[base + j + 3];
        float4 x0 = ((const float4*)&X[v0 * IN_DIM])[lane];
        float4 x1 = ((const float4*)&X[v1 * IN_DIM])[lane];
        float4 x2 = ((const float4*)&X[v2 * IN_DIM])[lane];
        float4 x3 = ((const float4*)&X[v3 * IN_DIM])[lane];
        a0.x += x0.x; a0.y += x0.y; a0.z += x0.z; a0.w += x0.w;
        a1.x += x1.x; a1.y += x1.y; a1.z += x1.z; a1.w += x1.w;
        a2.x += x2.x; a2.y += x2.y; a2.z += x2.z; a2.w += x2.w;
        a3.x += x3.x; a3.y += x3.y; a3.z += x3.z; a3.w += x3.w;
    }
    for (; j < cnt; j++) {
        float4 x0 = ((const float4*)&X[g_emem[base + j] * IN_DIM])[lane];
        a0.x += x0.x; a0.y += x0.y; a0.z += x0.z; a0.w += x0.w;
    }
    float inv = 1.0f / (float)(cnt > 0 ? cnt : 1);
    float4 r;
    r.x = (a0.x + a1.x + a2.x + a3.x) * inv;
    r.y = (a0.y + a1.y + a2.y + a3.y) * inv;
    r.z = (a0.z + a1.z + a2.z + a3.z) * inv;
    r.w = (a0.w + a1.w + a2.w + a3.w) * inv;
    ((float4*)&g_SumX[e * HC])[lane] = r;
}

// ------- Xe = SumX @ W^T + fused attention logits (alpha) ---------------------
__global__ void k_gemm(const float* __restrict__ W, const float* __restrict__ att,
                       int E) {
    __shared__ __align__(16) float As[16][68];
    __shared__ __align__(16) float Bs[16][64];
    int tid = threadIdx.x;
    int tx = tid & 15, ty = tid >> 4;
    int lane = tid & 31;
    int row0 = blockIdx.y * 64, col0 = blockIdx.x * 64;
    unsigned long long c2[4][2] = {};
    int r = tid >> 2, sseg = tid & 3;
    float4 attv = *(const float4*)&att[col0 + tx * 4];

    for (int k0 = 0; k0 < IN_DIM; k0 += 16) {
        float4 av;
        int arow = row0 + r;
        if (arow < E) av = *(const float4*)&g_SumX[arow * HC + k0 + sseg * 4];
        else          av = make_float4(0.f, 0.f, 0.f, 0.f);
        As[sseg * 4 + 0][r] = av.x;
        As[sseg * 4 + 1][r] = av.y;
        As[sseg * 4 + 2][r] = av.z;
        As[sseg * 4 + 3][r] = av.w;
        float4 bv = *(const float4*)&W[(col0 + r) * IN_DIM + k0 + sseg * 4];
        Bs[sseg * 4 + 0][r] = bv.x;
        Bs[sseg * 4 + 1][r] = bv.y;
        Bs[sseg * 4 + 2][r] = bv.z;
        Bs[sseg * 4 + 3][r] = bv.w;
        __syncthreads();
#pragma unroll
        for (int kk = 0; kk < 16; kk++) {
            float4 a = *(const float4*)&As[kk][ty * 4];
            float4 b = *(const float4*)&Bs[kk][tx * 4];
            unsigned long long b01, b23, ap;
            PACK2(b01, b.x, b.y);
            PACK2(b23, b.z, b.w);
            PACK2(ap, a.x, a.x); FMA2(c2[0][0], ap, b01); FMA2(c2[0][1], ap, b23);
            PACK2(ap, a.y, a.y); FMA2(c2[1][0], ap, b01); FMA2(c2[1][1], ap, b23);
            PACK2(ap, a.z, a.z); FMA2(c2[2][0], ap, b01); FMA2(c2[2][1], ap, b23);
            PACK2(ap, a.w, a.w); FMA2(c2[3][0], ap, b01); FMA2(c2[3][1], ap, b23);
        }
        __syncthreads();
    }
#pragma unroll
    for (int i = 0; i < 4; i++) {
        int row = row0 + ty * 4 + i;
        float x0, x1, x2, x3;
        UNPACK2(x0, x1, c2[i][0]);
        UNPACK2(x2, x3, c2[i][1]);
        if (row < E)
            *(float4*)&g_Xe[row * HC + col0 + tx * 4] = make_float4(x0, x1, x2, x3);
        float s = x0 * attv.x + x1 * attv.y + x2 * attv.z + x3 * attv.w;
        s += __shfl_xor_sync(0xffffffffu, s, 1);
        s += __shfl_xor_sync(0xffffffffu, s, 2);
        s += __shfl_xor_sync(0xffffffffu, s, 4);
        if ((lane & 7) == 0 && row < E) {
            int head = (col0 >> 5) + ((lane >> 3) & 1);
            g_alpha[row * H_ + head] = (s > 0.f) ? s : NEG_SLOPE * s;
        }
    }
}

// ---------------- per-vertex softmax + weighted sum + L2 norm -----------------
// 4 vertices / block, 64 threads / vertex, float4/thread; loops unrolled x4
// with batched index loads so 4 gathers are in flight per step.
__global__ void k_final(float* __restrict__ out, int N) {
    int g = threadIdx.x >> 6;                  // vertex slot in block (0..3)
    int v = blockIdx.x * 4 + g;
    int lane = threadIdx.x & 63;               // channels [4*lane, 4*lane+4)
    int h = lane >> 3;
    __shared__ float red[8];
    float4 val = make_float4(0.f, 0.f, 0.f, 0.f);
    int deg = g_cnt_v[v];
    int base = g_off_v[v] + g_bsum_v[v >> 10];
    if (deg > 0) {
        float m = -3.4e38f;
        int j = 0;
        for (; j + 4 <= deg; j += 4) {
            int e0 = g_vmem[base + j + 0];
            int e1 = g_vmem[base + j + 1];
            int e2 = g_vmem[base + j + 2];
            int e3 = g_vmem[base + j + 3];
            float a0 = g_alpha[e0 * H_ + h];
            float a1 = g_alpha[e1 * H_ + h];
            float a2 = g_alpha[e2 * H_ + h];
            float a3 = g_alpha[e3 * H_ + h];
            m = fmaxf(m, fmaxf(fmaxf(a0, a1), fmaxf(a2, a3)));
        }
        for (; j < deg; j++)
            m = fmaxf(m, g_alpha[g_vmem[base + j] * H_ + h]);
        float s = 0.f;
        j = 0;
        for (; j + 4 <= deg; j += 4) {
            int e0 = g_vmem[base + j + 0];
            int e1 = g_vmem[base + j + 1];
            int e2 = g_vmem[base + j + 2];
            int e3 = g_vmem[base + j + 3];
            float w0 = __expf(g_alpha[e0 * H_ + h] - m);
            float w1 = __expf(g_alpha[e1 * H_ + h] - m);
            float w2 = __expf(g_alpha[e2 * H_ + h] - m);
            float w3 = __expf(g_alpha[e3 * H_ + h] - m);
            float4 x0 = ((const float4*)&g_Xe[e0 * HC])[lane];
            float4 x1 = ((const float4*)&g_Xe[e1 * HC])[lane];
            float4 x2 = ((const float4*)&g_Xe[e2 * HC])[lane];
            float4 x3 = ((const float4*)&g_Xe[e3 * HC])[lane];
            s += w0 + w1 + w2 + w3;
            val.x = fmaf(w0, x0.x, fmaf(w1, x1.x, fmaf(w2, x2.x, fmaf(w3, x3.x, val.x))));
            val.y = fmaf(w0, x0.y, fmaf(w1, x1.y, fmaf(w2, x2.y, fmaf(w3, x3.y, val.y))));
            val.z = fmaf(w0, x0.z, fmaf(w1, x1.z, fmaf(w2, x2.z, fmaf(w3, x3.z, val.z))));
            val.w = fmaf(w0, x0.w, fmaf(w1, x1.w, fmaf(w2, x2.w, fmaf(w3, x3.w, val.w))));
        }
        for (; j < deg; j++) {
            int e = g_vmem[base + j];
            float w = __expf(g_alpha[e * H_ + h] - m);
            s += w;
            float4 xe = ((const float4*)&g_Xe[e * HC])[lane];
            val.x = fmaf(w, xe.x, val.x);
            val.y = fmaf(w, xe.y, val.y);
            val.z = fmaf(w, xe.z, val.z);
            val.w = fmaf(w, xe.w, val.w);
        }
        float inv = 1.0f / (s + 1e-16f);
        val.x *= inv; val.y *= inv; val.z *= inv; val.w *= inv;
    }
    float ss = val.x * val.x + val.y * val.y + val.z * val.z + val.w * val.w;
#pragma unroll
    for (int o = 16; o > 0; o >>= 1) ss += __shfl_down_sync(0xffffffffu, ss, o);
    if ((threadIdx.x & 31) == 0) red[threadIdx.x >> 5] = ss;
    __syncthreads();
    float tot = red[2 * g] + red[2 * g + 1];
    float scale = (tot > 0.f) ? rsqrtf(tot) : 0.f;
    val.x *= scale; val.y *= scale; val.z *= scale; val.w *= scale;
    ((float4*)&out[v * HC])[lane] = val;
}

// ---------------- host launch -------------------------------------------------
extern "C" void kernel_launch(void* const* d_in, const int* in_sizes, int n_in,
                              void* d_out, int out_size) {
    const float* X    = (const float*)d_in[0];
    const float* W    = (const float*)d_in[1];
    const float* att  = (const float*)d_in[2];
    const void*  vert = d_in[3];
    const void*  edge = d_in[4];

    int N   = in_sizes[0] / IN_DIM;
    int NNZ = in_sizes[3];
    int E   = EMAX;                 // fixed problem instance (num_edges = 10000)
    if (N   > NMAX)   N   = NMAX;
    if (NNZ > NNZMAX) NNZ = NNZMAX;

    k_zero<<<256, 256>>>((const int*)vert, NNZ, E, N);
    int hg = (NNZ + 255) / 256;
    if (hg > 2048) hg = 2048;
    k_hist<<<hg, 256>>>(vert, edge, NNZ);
    k_scan1<<<EB + VB, 1024>>>(E, N);
    k_fill<<<hg, 256>>>(vert, edge, NNZ);
    k_sumx<<<E / 4, 256>>>(X);
    dim3 gg(HC / 64, (E + 63) / 64);
    k_gemm<<<gg, 256>>>(W, att, E);
    k_final<<<N / 4, 256>>>((float*)d_out, N);
}